// round 4
// baseline (speedup 1.0000x reference)
#include <cuda_runtime.h>
#include <math.h>

#define LTOT 13326
#define LPAD 13440     // 105*128, padded
#define NQ   4096
#define GUARD 4096

__constant__ int   c_off[5]   = {0, 4096, 7345, 9946, 11882};
__constant__ int   c_ws[5]    = {64, 57, 51, 44, 38};
__constant__ float c_ratio[5] = {1.0f, 63.0f/56.0f, 63.0f/50.0f, 63.0f/43.0f, 63.0f/37.0f};

__device__ __align__(16) float g_mb  [2*32*NQ];
__device__ __align__(16) float g_m   [(size_t)2*32*LPAD];
__device__ __align__(16) float g_base[(size_t)2*64*LPAD];
__device__ __align__(16) float g_sq  [2*LPAD];
__device__ __align__(16) float g_invn[2*LPAD];
__device__ __align__(16) unsigned g_meta[LPAD];
__device__ __align__(16) float g_G   [(size_t)2*NQ*LPAD + 2*GUARD]; // G, then W
__device__ __align__(16) float g_P   [(size_t)2*NQ*LPAD + 2*GUARD]; // softmax probs
__device__ __align__(16) float g_part[(size_t)8*2*64*NQ];

// ---------------- helpers ----------------
__device__ __forceinline__ float cubw(float d) {
    d = fabsf(d);
    if (d <= 1.0f) return ((1.25f*d - 2.25f)*d)*d + 1.0f;
    if (d <  2.0f) return ((-0.75f*d + 3.75f)*d - 6.0f)*d + 3.0f;
    return 0.0f;
}

__device__ __forceinline__ float fexp(float x) {
    float t = fmaxf(x * 1.4426950408889634f, -125.0f);
    int   ri = __float2int_rn(t);
    float f  = t - (float)ri;
    float z  = f * 0.6931471805599453f;
    float p  = 1.0f + z*(1.0f + z*(0.5f + z*(0.16666667f + z*(0.041666667f + z*0.0083333333f))));
    return __int_as_float((ri + 127) << 23) * p;
}

// load 4-float window at arbitrary (possibly negative) offset o of a row
__device__ __forceinline__ void ldwin4(const float* p, int o, float w[4]) {
    const float* ap = p + (o & ~3);
    int d = o & 3;
    float4 lo = *(const float4*)ap;
    if (d == 0) { w[0]=lo.x; w[1]=lo.y; w[2]=lo.z; w[3]=lo.w; return; }
    float4 hi = *(const float4*)(ap + 4);
    if (d == 1)      { w[0]=lo.y; w[1]=lo.z; w[2]=lo.w; w[3]=hi.x; }
    else if (d == 2) { w[0]=lo.z; w[1]=lo.w; w[2]=hi.x; w[3]=hi.y; }
    else             { w[0]=lo.w; w[1]=hi.x; w[2]=hi.y; w[3]=hi.z; }
}

// ---------------- stage 0: match_base ----------------
__global__ void k_matchbase(const float* __restrict__ inp, const float* __restrict__ Wb,
                            const float* __restrict__ bb, const float* __restrict__ ap) {
    int idx = blockIdx.x * blockDim.x + threadIdx.x;
    if (idx >= 2*32*4096) return;
    int pos = idx & 4095;
    int cm  = (idx >> 12) & 31;
    int b   = idx >> 17;
    const float* x = inp + ((size_t)b*64)*4096 + pos;
    const float* w = Wb + cm*64;
    float acc = bb[cm];
#pragma unroll
    for (int c = 0; c < 64; c++) acc = fmaf(w[c], x[(size_t)c*4096], acc);
    float a = ap[0];
    g_mb[idx] = acc >= 0.0f ? acc : a*acc;
}

// ---------------- stage 1: resize + conv_match/assembly ----------------
__global__ __launch_bounds__(128) void k_resize_conv(const float* __restrict__ ref,
        const float* __restrict__ Wm, const float* __restrict__ bmv,
        const float* __restrict__ Wa, const float* __restrict__ ba,
        const float* __restrict__ ap) {
    __shared__ float Wsh[96][65];
    __shared__ float bsh[96];
    __shared__ float rv[8][65];
    int b = blockIdx.y;
    int t = threadIdx.x;
    for (int i = t; i < 96*64; i += 128) {
        int o = i >> 6, c = i & 63;
        Wsh[o][c] = (o < 32) ? Wm[o*64 + c] : Wa[(o-32)*64 + c];
    }
    if (t < 96) bsh[t] = (t < 32) ? bmv[t] : ba[t-32];
    float a = ap[0];
    int p0 = blockIdx.x * 8;

    for (int i = t; i < 512; i += 128) {
        int c = i >> 3, pi = i & 7;
        int pos = p0 + pi;
        float val = 0.0f;
        if (pos < LTOT) {
            int s = 0;
            while (s < 4 && pos >= c_off[s+1]) s++;
            int lp = pos - c_off[s];
            int ws = c_ws[s];
            int y = lp / ws, x = lp - y*ws;
            float ratio = c_ratio[s];
            float ry = (float)y * ratio, rx = (float)x * ratio;
            int iy0 = (int)floorf(ry); float fy = ry - (float)iy0;
            int ix0 = (int)floorf(rx); float fx = rx - (float)ix0;
            float wyv[4] = {cubw(fy+1.0f), cubw(fy), cubw(1.0f-fy), cubw(2.0f-fy)};
            float wxv[4] = {cubw(fx+1.0f), cubw(fx), cubw(1.0f-fx), cubw(2.0f-fx)};
            const float* ch = ref + ((size_t)b*64 + c)*4096;
#pragma unroll
            for (int u = 0; u < 4; u++) {
                int yy = min(max(iy0 - 1 + u, 0), 63);
                const float* rowp = ch + yy*64;
                float racc = 0.0f;
#pragma unroll
                for (int v = 0; v < 4; v++) {
                    int xx = min(max(ix0 - 1 + v, 0), 63);
                    racc = fmaf(wxv[v], rowp[xx], racc);
                }
                val = fmaf(wyv[u], racc, val);
            }
        }
        rv[pi][c] = val;
    }
    __syncthreads();

    for (int i = t; i < 768; i += 128) {
        int pi = i / 96, o = i % 96;
        int pos = p0 + pi;
        if (pos >= LTOT) continue;
        float acc = bsh[o];
#pragma unroll
        for (int c = 0; c < 64; c++) acc = fmaf(Wsh[o][c], rv[pi][c], acc);
        acc = acc >= 0.0f ? acc : a*acc;
        if (o < 32) g_m   [((size_t)b*32 + o)     *LPAD + pos] = acc;
        else        g_base[((size_t)b*64 + (o-32))*LPAD + pos] = acc;
    }
}

// ---------------- stage 2a: meta, sq, pad zeroing ----------------
__global__ void k_prep() {
    int l = blockIdx.x*128 + threadIdx.x;
    if (l >= LPAD) return;
    if (l >= LTOT) {
        g_meta[l] = 1u;   // ws=1, mask=0
        for (int r = 0; r < 64;  r++) g_m   [(size_t)r*LPAD + l] = 0.0f;
        for (int r = 0; r < 128; r++) g_base[(size_t)r*LPAD + l] = 0.0f;
        g_sq[l] = 0.0f; g_sq[LPAD + l] = 0.0f;
        return;
    }
    int s = 0;
    while (s < 4 && l >= c_off[s+1]) s++;
    int ws = c_ws[s], lp = l - c_off[s];
    int ly = lp / ws, lx = lp - ly*ws;
    unsigned mask = 0;
#pragma unroll
    for (int dy = -1; dy <= 1; dy++)
#pragma unroll
        for (int dx = -1; dx <= 1; dx++) {
            int yy = ly+dy, xx = lx+dx;
            if (yy >= 0 && yy < ws && xx >= 0 && xx < ws)
                mask |= 1u << ((dy+1)*3 + (dx+1));
        }
    g_meta[l] = (unsigned)ws | (mask << 8);
#pragma unroll
    for (int b = 0; b < 2; b++) {
        float a = 0.0f;
        for (int c = 0; c < 32; c++) {
            float v = g_m[((size_t)b*32 + c)*LPAD + l];
            a = fmaf(v, v, a);
        }
        g_sq[b*LPAD + l] = a;
    }
}

// ---------------- stage 2b: invn = 10 / max(sqrt(9-tap sq), 1e-4) ----------------
__global__ void k_invnrm() {
    int l = blockIdx.x*128 + threadIdx.x;
    int b = blockIdx.y;
    if (l >= LPAD) return;
    if (l >= LTOT) { g_invn[b*LPAD + l] = 0.0f; return; }
    unsigned mt = g_meta[l];
    int ws = (int)(mt & 255u);
    float a = 0.0f;
#pragma unroll
    for (int dy = -1; dy <= 1; dy++)
#pragma unroll
        for (int dx = -1; dx <= 1; dx++) {
            int bi = (dy+1)*3 + (dx+1);
            if ((mt >> (8 + bi)) & 1u) a += g_sq[b*LPAD + l + dy*ws + dx];
        }
    g_invn[b*LPAD + l] = 10.0f / fmaxf(sqrtf(a), 1e-4f);
}

// ---------------- stage 3: G = mb^T * m  (M=4096, N=13440, K=32) ----------------
__global__ __launch_bounds__(256) void k_gemm_G() {
    const int b  = blockIdx.z;
    const int bm = blockIdx.y << 7;
    const int bn = blockIdx.x << 7;
    const float* A  = g_mb + (size_t)b*32*NQ;
    const float* Bm = g_m  + (size_t)b*32*LPAD;
    float* G = g_G + GUARD + (size_t)b*NQ*LPAD;
    __shared__ float As[32][128];
    __shared__ float Bs[32][128];
    const int t = threadIdx.x;
#pragma unroll
    for (int j = 0; j < 4; j++) {
        int id = t + j*256;
        int row = id >> 5, c4 = (id & 31) << 2;
        *(float4*)&As[row][c4] = *(const float4*)(A  + (size_t)row*NQ   + bm + c4);
        *(float4*)&Bs[row][c4] = *(const float4*)(Bm + (size_t)row*LPAD + bn + c4);
    }
    __syncthreads();
    const int ty = t >> 4, tx = t & 15;
    float acc[8][8] = {};
#pragma unroll
    for (int kk = 0; kk < 32; kk++) {
        float4 a0 = *(const float4*)&As[kk][ty << 3];
        float4 a1 = *(const float4*)&As[kk][(ty << 3) + 4];
        float4 b0 = *(const float4*)&Bs[kk][tx << 3];
        float4 b1 = *(const float4*)&Bs[kk][(tx << 3) + 4];
        float ra[8] = {a0.x,a0.y,a0.z,a0.w,a1.x,a1.y,a1.z,a1.w};
        float rb[8] = {b0.x,b0.y,b0.z,b0.w,b1.x,b1.y,b1.z,b1.w};
#pragma unroll
        for (int i = 0; i < 8; i++)
#pragma unroll
            for (int j = 0; j < 8; j++)
                acc[i][j] = fmaf(ra[i], rb[j], acc[i][j]);
    }
#pragma unroll
    for (int i = 0; i < 8; i++) {
        float* row = G + (size_t)(bm + (ty << 3) + i)*LPAD + bn + (tx << 3);
        *(float4*)row     = make_float4(acc[i][0],acc[i][1],acc[i][2],acc[i][3]);
        *(float4*)(row+4) = make_float4(acc[i][4],acc[i][5],acc[i][6],acc[i][7]);
    }
}

// ---------------- stages 4/5: 9-tap shift (+softmax for SM variant) ----------------
template<bool SM>
__global__ __launch_bounds__(256) void k_shift() {
    const int q = blockIdx.x, b = blockIdx.y;
    const int y = q >> 6, x = q & 63;
    unsigned qmask = 0;
#pragma unroll
    for (int dy = -1; dy <= 1; dy++)
#pragma unroll
        for (int dx = -1; dx <= 1; dx++) {
            int yy = y+dy, xx = x+dx;
            if (yy >= 0 && yy < 64 && xx >= 0 && xx < 64)
                qmask |= 1u << ((dy+1)*3 + (dx+1));
        }
    const float* srcbase = (SM ? g_G : g_P) + GUARD + (size_t)b*NQ*LPAD;
    float* dst = (SM ? g_P : g_G) + GUARD + ((size_t)b*NQ + q)*LPAD;
    const float* R[9];
#pragma unroll
    for (int dy = -1; dy <= 1; dy++)
#pragma unroll
        for (int dx = -1; dx <= 1; dx++)
            R[(dy+1)*3 + (dx+1)] = srcbase + (size_t)(q + dy*64 + dx)*LPAD;

    const int t = threadIdx.x;
    extern __shared__ float srow[];
    __shared__ float red[8];
    __shared__ float bcast;
    float lmax = -1e30f;

    for (int g = t; g < LPAD/4; g += 256) {
        int l4 = g << 2;
        uint4 mt = *(const uint4*)(g_meta + l4);
        unsigned m0 = (mt.x>>8)&qmask, m1 = (mt.y>>8)&qmask,
                 m2 = (mt.z>>8)&qmask, m3 = (mt.w>>8)&qmask;
        unsigned anym = m0|m1|m2|m3;
        float acc[4] = {0.f,0.f,0.f,0.f};
        if (anym) {
            int ws0 = (int)(mt.x & 255u), ws3 = (int)(mt.w & 255u);
            if (ws0 == ws3) {
#pragma unroll
                for (int dy = -1; dy <= 1; dy++)
#pragma unroll
                    for (int dx = -1; dx <= 1; dx++) {
                        const int bi = (dy+1)*3 + (dx+1);
                        if (!((anym >> bi) & 1u)) continue;
                        float w[4];
                        ldwin4(R[bi], l4 + dy*ws0 + dx, w);
                        if ((m0>>bi)&1u) acc[0] += w[0];
                        if ((m1>>bi)&1u) acc[1] += w[1];
                        if ((m2>>bi)&1u) acc[2] += w[2];
                        if ((m3>>bi)&1u) acc[3] += w[3];
                    }
            } else {
                unsigned mm[4] = {m0,m1,m2,m3};
                int wss[4] = {(int)(mt.x&255u),(int)(mt.y&255u),(int)(mt.z&255u),(int)(mt.w&255u)};
#pragma unroll
                for (int e = 0; e < 4; e++) {
#pragma unroll
                    for (int dy = -1; dy <= 1; dy++)
#pragma unroll
                        for (int dx = -1; dx <= 1; dx++) {
                            int bi = (dy+1)*3 + (dx+1);
                            if ((mm[e] >> bi) & 1u) acc[e] += R[bi][l4+e + dy*wss[e] + dx];
                        }
                }
            }
        }
        if (SM) {
            float4 iv = *(const float4*)(g_invn + b*LPAD + l4);
            float s0 = (l4+0 < LTOT) ? acc[0]*iv.x : -1e30f;
            float s1 = (l4+1 < LTOT) ? acc[1]*iv.y : -1e30f;
            float s2 = (l4+2 < LTOT) ? acc[2]*iv.z : -1e30f;
            float s3 = (l4+3 < LTOT) ? acc[3]*iv.w : -1e30f;
            *(float4*)(srow + l4) = make_float4(s0,s1,s2,s3);
            lmax = fmaxf(lmax, fmaxf(fmaxf(s0,s1), fmaxf(s2,s3)));
        } else {
            *(float4*)(dst + l4) = make_float4(acc[0],acc[1],acc[2],acc[3]);
        }
    }
    if (SM) {
#pragma unroll
        for (int o = 16; o > 0; o >>= 1) lmax = fmaxf(lmax, __shfl_xor_sync(0xffffffffu, lmax, o));
        if ((t & 31) == 0) red[t >> 5] = lmax;
        __syncthreads();
        if (t == 0) {
            float m = red[0];
#pragma unroll
            for (int i = 1; i < 8; i++) m = fmaxf(m, red[i]);
            bcast = m;
        }
        __syncthreads();
        float M = bcast;
        float lsum = 0.0f;
        for (int g = t; g < LPAD/4; g += 256) {
            int l4 = g << 2;
            float4 v = *(float4*)(srow + l4);
            float4 e = make_float4(fexp(v.x-M), fexp(v.y-M), fexp(v.z-M), fexp(v.w-M));
            *(float4*)(srow + l4) = e;
            lsum += (e.x + e.y) + (e.z + e.w);
        }
#pragma unroll
        for (int o = 16; o > 0; o >>= 1) lsum += __shfl_xor_sync(0xffffffffu, lsum, o);
        __syncthreads();
        if ((t & 31) == 0) red[t >> 5] = lsum;
        __syncthreads();
        if (t == 0) {
            float s = 0.0f;
#pragma unroll
            for (int i = 0; i < 8; i++) s += red[i];
            bcast = 1.0f / s;
        }
        __syncthreads();
        float inv = bcast;
        for (int g = t; g < LPAD/4; g += 256) {
            int l4 = g << 2;
            float4 e = *(float4*)(srow + l4);
            *(float4*)(dst + l4) = make_float4(e.x*inv, e.y*inv, e.z*inv, e.w*inv);
        }
    }
}

// ---------------- stage 6: out_part = W * base^T (split-K=8) ----------------
__global__ __launch_bounds__(256) void k_gemm_W() {
    const int split = blockIdx.x;          // 0..7
    const int bm = blockIdx.y << 7;        // 32 blocks
    const int b  = blockIdx.z;
    const float* W  = g_G + GUARD + (size_t)b*NQ*LPAD;
    const float* Bb = g_base + (size_t)b*64*LPAD;
    __shared__ float As[8][128];
    __shared__ float Bs[8][64];
    const int t = threadIdx.x;
    const int ty = t >> 4, tx = t & 15;
    float acc[8][4] = {};
    const int kbeg = split * (LPAD/8);
    const int arow = t >> 1, akc = (t & 1) << 2;
    const float* Aptr = W + (size_t)(bm + arow)*LPAD + akc;
    const int brow = (t & 127) >> 1;
    const float* Bptr = Bb + (size_t)brow*LPAD + akc;

    for (int k0 = kbeg; k0 < kbeg + LPAD/8; k0 += 8) {
        float4 a4 = *(const float4*)(Aptr + k0);
        As[akc+0][arow] = a4.x; As[akc+1][arow] = a4.y;
        As[akc+2][arow] = a4.z; As[akc+3][arow] = a4.w;
        if (t < 128) {
            float4 b4 = *(const float4*)(Bptr + k0);
            Bs[akc+0][brow] = b4.x; Bs[akc+1][brow] = b4.y;
            Bs[akc+2][brow] = b4.z; Bs[akc+3][brow] = b4.w;
        }
        __syncthreads();
#pragma unroll
        for (int kk = 0; kk < 8; kk++) {
            float4 a0 = *(const float4*)&As[kk][ty << 3];
            float4 a1 = *(const float4*)&As[kk][(ty << 3) + 4];
            float4 b0 = *(const float4*)&Bs[kk][tx << 2];
            float ra[8] = {a0.x,a0.y,a0.z,a0.w,a1.x,a1.y,a1.z,a1.w};
            float rb[4] = {b0.x,b0.y,b0.z,b0.w};
#pragma unroll
            for (int i = 0; i < 8; i++)
#pragma unroll
                for (int j = 0; j < 4; j++)
                    acc[i][j] = fmaf(ra[i], rb[j], acc[i][j]);
        }
        __syncthreads();
    }
    float* pb = g_part + (size_t)(split*2 + b)*64*NQ;
#pragma unroll
    for (int j = 0; j < 4; j++) {
        int c = (tx << 2) + j;
        float4 v0 = make_float4(acc[0][j],acc[1][j],acc[2][j],acc[3][j]);
        float4 v1 = make_float4(acc[4][j],acc[5][j],acc[6][j],acc[7][j]);
        *(float4*)(pb + (size_t)c*NQ + bm + (ty << 3))     = v0;
        *(float4*)(pb + (size_t)c*NQ + bm + (ty << 3) + 4) = v1;
    }
}

// ---------------- stage 7: reduce partials + residual ----------------
__global__ void k_final(const float* __restrict__ inp, float* __restrict__ out) {
    int idx = blockIdx.x * blockDim.x + threadIdx.x;   // 2*64*4096
    if (idx >= 2*64*4096) return;
    int q = idx & 4095;
    int c = (idx >> 12) & 63;
    int b = idx >> 18;
    float s = 0.0f;
#pragma unroll
    for (int sp = 0; sp < 8; sp++)
        s += g_part[(size_t)(sp*2 + b)*64*NQ + (size_t)c*NQ + q];
    out[idx] = inp[idx] + 0.25f * s;
}

// ---------------- launch ----------------
extern "C" void kernel_launch(void* const* d_in, const int* in_sizes, int n_in,
                              void* d_out, int out_size) {
    const float* input     = (const float*)d_in[0];
    const float* input_ref = (const float*)d_in[1];
    const float* Wb  = (const float*)d_in[2];
    const float* bbv = (const float*)d_in[3];
    const float* Wm  = (const float*)d_in[4];
    const float* bmv = (const float*)d_in[5];
    const float* Wa  = (const float*)d_in[6];
    const float* bav = (const float*)d_in[7];
    const float* ap  = (const float*)d_in[8];
    float* out = (float*)d_out;

    cudaFuncSetAttribute(k_shift<true>, cudaFuncAttributeMaxDynamicSharedMemorySize, LPAD*4);

    k_matchbase  <<<1024, 256>>>(input, Wb, bbv, ap);
    k_resize_conv<<<dim3(1666, 2), 128>>>(input_ref, Wm, bmv, Wa, bav, ap);
    k_prep       <<<105, 128>>>();
    k_invnrm     <<<dim3(105, 2), 128>>>();
    k_gemm_G     <<<dim3(105, 32, 2), 256>>>();
    k_shift<true> <<<dim3(NQ, 2), 256, LPAD*4>>>();
    k_shift<false><<<dim3(NQ, 2), 256>>>();
    k_gemm_W     <<<dim3(8, 32, 2), 256>>>();
    k_final      <<<2048, 256>>>(input, out);
}

// round 7
// speedup vs baseline: 1.0797x; 1.0797x over previous
#include <cuda_runtime.h>
#include <math.h>

#define LTOT  13326
#define LPAD2 14464     // padded grids: 66^2,59^2,53^2,46^2,40^2 + gaps
#define NQ    4096
#define GUARD 4096
#define NG8   (LPAD2/8)

__constant__ int   c_off [5] = {0, 4096, 7345, 9946, 11882};
__constant__ int   c_off2[5] = {0, 4368, 7856, 10672, 12800};
__constant__ int   c_ws  [5] = {64, 57, 51, 44, 38};
__constant__ float c_ratio[5]= {1.0f, 63.0f/56.0f, 63.0f/50.0f, 63.0f/43.0f, 63.0f/37.0f};

__device__ __align__(16) float g_mb  [2*32*NQ];
__device__ __align__(16) float g_m   [(size_t)2*32*LPAD2];
__device__ __align__(16) float g_base[(size_t)2*64*LPAD2];
__device__ __align__(16) float g_sq  [2*LPAD2];
__device__ __align__(16) float g_invb[(size_t)2*2*LPAD2];            // (10/nrm, bias)
__device__ __align__(16) float g_G   [(size_t)2*NQ*LPAD2 + 2*GUARD]; // G, then H_P
__device__ __align__(16) float g_P   [(size_t)2*NQ*LPAD2 + 2*GUARD]; // E
__device__ __align__(16) float g_H   [(size_t)2*NQ*LPAD2 + 2*GUARD]; // H_G, then W
__device__ __align__(16) float g_invs[2*NQ];
__device__ __align__(16) float g_part[(size_t)8*2*64*NQ];

__device__ __forceinline__ float cubw(float d) {
    d = fabsf(d);
    if (d <= 1.0f) return ((1.25f*d - 2.25f)*d)*d + 1.0f;
    if (d <  2.0f) return ((-0.75f*d + 3.75f)*d - 6.0f)*d + 3.0f;
    return 0.0f;
}
__device__ __forceinline__ float fexp(float x) {
    float t = fmaxf(x * 1.4426950408889634f, -125.0f);
    int   ri = __float2int_rn(t);
    float f  = t - (float)ri;
    float z  = f * 0.6931471805599453f;
    float p  = 1.0f + z*(1.0f + z*(0.5f + z*(0.16666667f + z*(0.041666667f + z*0.0083333333f))));
    return __int_as_float((ri + 127) << 23) * p;
}
__device__ __forceinline__ void ldwin8(const float* p, float w[8]) {
    int d = (int)((((size_t)p) >> 2) & 3);
    const float4* ap = (const float4*)(p - d);
    float4 A = ap[0], B = ap[1], C = B;
    if (d) C = ap[2];
    if (d == 0)      { w[0]=A.x;w[1]=A.y;w[2]=A.z;w[3]=A.w;w[4]=B.x;w[5]=B.y;w[6]=B.z;w[7]=B.w; }
    else if (d == 1) { w[0]=A.y;w[1]=A.z;w[2]=A.w;w[3]=B.x;w[4]=B.y;w[5]=B.z;w[6]=B.w;w[7]=C.x; }
    else if (d == 2) { w[0]=A.z;w[1]=A.w;w[2]=B.x;w[3]=B.y;w[4]=B.z;w[5]=B.w;w[6]=C.x;w[7]=C.y; }
    else             { w[0]=A.w;w[1]=B.x;w[2]=B.y;w[3]=B.z;w[4]=B.w;w[5]=C.x;w[6]=C.y;w[7]=C.z; }
}
__device__ __forceinline__ int stride_of(int l) {
    if (l < 4368)  return 66;
    if (l < 7856)  return 59;
    if (l < 10672) return 53;
    if (l < 12800) return 46;
    return 40;
}

// ---------------- zero m/base ----------------
__global__ void k_zero() {
    size_t i = (size_t)blockIdx.x*blockDim.x + threadIdx.x;
    size_t nm = (size_t)2*32*LPAD2/4, nb = (size_t)2*64*LPAD2/4;
    float4 z = make_float4(0.f,0.f,0.f,0.f);
    for (; i < nm + nb; i += (size_t)gridDim.x*blockDim.x) {
        if (i < nm) ((float4*)g_m)[i] = z;
        else ((float4*)g_base)[i - nm] = z;
    }
}

// ---------------- match_base ----------------
__global__ void k_matchbase(const float* __restrict__ inp, const float* __restrict__ Wb,
                            const float* __restrict__ bb, const float* __restrict__ ap) {
    int idx = blockIdx.x * blockDim.x + threadIdx.x;
    if (idx >= 2*32*4096) return;
    int pos = idx & 4095, cm = (idx >> 12) & 31, b = idx >> 17;
    const float* x = inp + ((size_t)b*64)*4096 + pos;
    const float* w = Wb + cm*64;
    float acc = bb[cm];
#pragma unroll
    for (int c = 0; c < 64; c++) acc = fmaf(w[c], x[(size_t)c*4096], acc);
    float a = ap[0];
    g_mb[idx] = acc >= 0.0f ? acc : a*acc;
}

// ---------------- resize + conv (writes padded layout) ----------------
__global__ __launch_bounds__(128) void k_resize_conv(const float* __restrict__ ref,
        const float* __restrict__ Wm, const float* __restrict__ bmv,
        const float* __restrict__ Wa, const float* __restrict__ bav,
        const float* __restrict__ ap) {
    __shared__ float Wsh[96][65];
    __shared__ float bsh[96];
    __shared__ float rv[8][65];
    __shared__ int   l2sh[8];
    int b = blockIdx.y, t = threadIdx.x;
    for (int i = t; i < 96*64; i += 128) {
        int o = i >> 6, c = i & 63;
        Wsh[o][c] = (o < 32) ? Wm[o*64 + c] : Wa[(o-32)*64 + c];
    }
    if (t < 96) bsh[t] = (t < 32) ? bmv[t] : bav[t-32];
    float a = ap[0];
    int p0 = blockIdx.x * 8;
    if (t < 8) {
        int pos = p0 + t, v = -1;
        if (pos < LTOT) {
            int s = 0;
            while (s < 4 && pos >= c_off[s+1]) s++;
            int ws = c_ws[s], lp = pos - c_off[s];
            int y = lp / ws, x = lp - y*ws;
            v = c_off2[s] + (y+1)*(ws+2) + (x+1);
        }
        l2sh[t] = v;
    }
    for (int i = t; i < 512; i += 128) {
        int c = i >> 3, pi = i & 7;
        int pos = p0 + pi;
        float val = 0.0f;
        if (pos < LTOT) {
            int s = 0;
            while (s < 4 && pos >= c_off[s+1]) s++;
            int lp = pos - c_off[s];
            int ws = c_ws[s];
            int y = lp / ws, x = lp - y*ws;
            float ry = (float)y * c_ratio[s], rx = (float)x * c_ratio[s];
            int iy0 = (int)floorf(ry); float fy = ry - (float)iy0;
            int ix0 = (int)floorf(rx); float fx = rx - (float)ix0;
            float wyv[4] = {cubw(fy+1.0f), cubw(fy), cubw(1.0f-fy), cubw(2.0f-fy)};
            float wxv[4] = {cubw(fx+1.0f), cubw(fx), cubw(1.0f-fx), cubw(2.0f-fx)};
            const float* ch = ref + ((size_t)b*64 + c)*4096;
#pragma unroll
            for (int u = 0; u < 4; u++) {
                int yy = min(max(iy0 - 1 + u, 0), 63);
                const float* rowp = ch + yy*64;
                float racc = 0.0f;
#pragma unroll
                for (int v = 0; v < 4; v++)
                    racc = fmaf(wxv[v], rowp[min(max(ix0 - 1 + v, 0), 63)], racc);
                val = fmaf(wyv[u], racc, val);
            }
        }
        rv[pi][c] = val;
    }
    __syncthreads();
    for (int i = t; i < 768; i += 128) {
        int pi = i / 96, o = i % 96;
        int l2 = l2sh[pi];
        if (l2 < 0) continue;
        float acc = bsh[o];
#pragma unroll
        for (int c = 0; c < 64; c++) acc = fmaf(Wsh[o][c], rv[pi][c], acc);
        acc = acc >= 0.0f ? acc : a*acc;
        if (o < 32) g_m   [((size_t)b*32 + o)     *LPAD2 + l2] = acc;
        else        g_base[((size_t)b*64 + (o-32))*LPAD2 + l2] = acc;
    }
}

// ---------------- sq ----------------
__global__ void k_prep() {
    int l = blockIdx.x*128 + threadIdx.x;
    int b = blockIdx.y;
    if (l >= LPAD2) return;
    float a = 0.0f;
#pragma unroll
    for (int c = 0; c < 32; c++) {
        float v = g_m[((size_t)b*32 + c)*LPAD2 + l];
        a = fmaf(v, v, a);
    }
    g_sq[b*LPAD2 + l] = a;
}

// ---------------- invb: (10/nrm, 0) at real cells else (0, -1e30) ----------------
__global__ void k_invb() {
    int l = blockIdx.x*128 + threadIdx.x;
    int b = blockIdx.y;
    if (l >= LPAD2) return;
    int wd = 0, loc = 0;
    if      (l < 4356)                { wd=66; loc=l; }
    else if (l >= 4368  && l < 7849)  { wd=59; loc=l-4368; }
    else if (l >= 7856  && l < 10665) { wd=53; loc=l-7856; }
    else if (l >= 10672 && l < 12788) { wd=46; loc=l-10672; }
    else if (l >= 12800 && l < 14400) { wd=40; loc=l-12800; }
    float2 o = make_float2(0.0f, -1e30f);
    if (wd) {
        int y = loc / wd, x = loc - y*wd;
        if (y >= 1 && y <= wd-2 && x >= 1 && x <= wd-2) {
            float a = 0.0f;
#pragma unroll
            for (int dy = -1; dy <= 1; dy++)
#pragma unroll
                for (int dx = -1; dx <= 1; dx++)
                    a += g_sq[b*LPAD2 + l + dy*wd + dx];
            o = make_float2(10.0f / fmaxf(sqrtf(a), 1e-4f), 0.0f);
        }
    }
    ((float2*)g_invb)[(size_t)b*LPAD2 + l] = o;
}

// ---------------- G = mb^T * m ----------------
__global__ __launch_bounds__(256) void k_gemm_G() {
    const int b  = blockIdx.z;
    const int bm = blockIdx.y << 7, bn = blockIdx.x << 7;
    const float* A  = g_mb + (size_t)b*32*NQ;
    const float* Bm = g_m  + (size_t)b*32*LPAD2;
    float* G = g_G + GUARD + (size_t)b*NQ*LPAD2;
    __shared__ float As[32][128];
    __shared__ float Bs[32][128];
    const int t = threadIdx.x;
#pragma unroll
    for (int j = 0; j < 4; j++) {
        int id = t + j*256;
        int row = id >> 5, c4 = (id & 31) << 2;
        *(float4*)&As[row][c4] = *(const float4*)(A  + (size_t)row*NQ    + bm + c4);
        *(float4*)&Bs[row][c4] = *(const float4*)(Bm + (size_t)row*LPAD2 + bn + c4);
    }
    __syncthreads();
    const int ty = t >> 4, tx = t & 15;
    float acc[8][8] = {};
#pragma unroll
    for (int kk = 0; kk < 32; kk++) {
        float4 a0 = *(const float4*)&As[kk][ty << 3];
        float4 a1 = *(const float4*)&As[kk][(ty << 3) + 4];
        float4 b0 = *(const float4*)&Bs[kk][tx << 3];
        float4 b1 = *(const float4*)&Bs[kk][(tx << 3) + 4];
        float ra[8] = {a0.x,a0.y,a0.z,a0.w,a1.x,a1.y,a1.z,a1.w};
        float rb[8] = {b0.x,b0.y,b0.z,b0.w,b1.x,b1.y,b1.z,b1.w};
#pragma unroll
        for (int i = 0; i < 8; i++)
#pragma unroll
            for (int j = 0; j < 8; j++)
                acc[i][j] = fmaf(ra[i], rb[j], acc[i][j]);
    }
#pragma unroll
    for (int i = 0; i < 8; i++) {
        float* row = G + (size_t)(bm + (ty << 3) + i)*LPAD2 + bn + (tx << 3);
        *(float4*)row     = make_float4(acc[i][0],acc[i][1],acc[i][2],acc[i][3]);
        *(float4*)(row+4) = make_float4(acc[i][4],acc[i][5],acc[i][6],acc[i][7]);
    }
}

// ---------------- H pass (device globals baked in; MODE 0: G->H_G, MODE 1: E->H_P scaled) ----
template<int MODE>
__global__ __launch_bounds__(256) void k_H() {
    int r = blockIdx.x, b = blockIdx.y;
    const float* src = (MODE == 0) ? g_G : g_P;
    float*       dst = (MODE == 0) ? g_H : g_G;
    const float* S = src + GUARD + ((size_t)b*NQ + r)*LPAD2;
    float* D = dst + GUARD + ((size_t)b*NQ + r)*LPAD2;
    int x = r & 63;
    bool lok = x > 0, rok = x < 63;
    float ivl = 1.0f, ivc = 1.0f, ivr = 1.0f;
    if (MODE == 1) {
        ivc = g_invs[b*NQ + r];
        if (lok) ivl = g_invs[b*NQ + r - 1];
        if (rok) ivr = g_invs[b*NQ + r + 1];
    }
    for (int g = threadIdx.x; g < NG8; g += 256) {
        int l8 = g << 3;
        float acc[8], w[8];
        float4 c0 = *(const float4*)(S + l8), c1 = *(const float4*)(S + l8 + 4);
        acc[0]=ivc*c0.x; acc[1]=ivc*c0.y; acc[2]=ivc*c0.z; acc[3]=ivc*c0.w;
        acc[4]=ivc*c1.x; acc[5]=ivc*c1.y; acc[6]=ivc*c1.z; acc[7]=ivc*c1.w;
        if (lok) {
            ldwin8(S - LPAD2 + l8 - 1, w);
#pragma unroll
            for (int e = 0; e < 8; e++) acc[e] = fmaf(ivl, w[e], acc[e]);
        }
        if (rok) {
            ldwin8(S + LPAD2 + l8 + 1, w);
#pragma unroll
            for (int e = 0; e < 8; e++) acc[e] = fmaf(ivr, w[e], acc[e]);
        }
        *(float4*)(D + l8)     = make_float4(acc[0],acc[1],acc[2],acc[3]);
        *(float4*)(D + l8 + 4) = make_float4(acc[4],acc[5],acc[6],acc[7]);
    }
}

// ---------------- score V pass + softmax: E rows + invs ----------------
__global__ __launch_bounds__(256) void k_scoreV() {
    int q = blockIdx.x, b = blockIdx.y;
    const float* S = g_H + GUARD + (size_t)b*NQ*LPAD2;
    float* D = g_P + GUARD + ((size_t)b*NQ + q)*LPAD2;
    const float2* ivb = ((const float2*)g_invb) + (size_t)b*LPAD2;
    int y = q >> 6, t = threadIdx.x;
    const float* up = S + (size_t)(q-64)*LPAD2;
    const float* md = S + (size_t)q*LPAD2;
    const float* dn = S + (size_t)(q+64)*LPAD2;
    bool uok = y > 0, dok = y < 63;
    float sreg[8][8];
    float mx = -3e38f;
#pragma unroll
    for (int it = 0; it < 8; it++) {
        int g = t + it*256;
        if (g >= NG8) break;
        int l8 = g << 3;
        int st = stride_of(l8);
        float acc[8], w[8];
        float4 m0 = *(const float4*)(md + l8), m1 = *(const float4*)(md + l8 + 4);
        acc[0]=m0.x; acc[1]=m0.y; acc[2]=m0.z; acc[3]=m0.w;
        acc[4]=m1.x; acc[5]=m1.y; acc[6]=m1.z; acc[7]=m1.w;
        if (uok) { ldwin8(up + l8 - st, w);
#pragma unroll
            for (int e = 0; e < 8; e++) acc[e] += w[e]; }
        if (dok) { ldwin8(dn + l8 + st, w);
#pragma unroll
            for (int e = 0; e < 8; e++) acc[e] += w[e]; }
#pragma unroll
        for (int k = 0; k < 4; k++) {
            float4 iv = *(const float4*)(ivb + l8 + 2*k);
            float s0 = fmaf(acc[2*k],   iv.x, iv.y);
            float s1 = fmaf(acc[2*k+1], iv.z, iv.w);
            sreg[it][2*k] = s0; sreg[it][2*k+1] = s1;
            mx = fmaxf(mx, fmaxf(s0, s1));
        }
    }
    __shared__ float red[8];
    __shared__ float bc;
#pragma unroll
    for (int o = 16; o > 0; o >>= 1) mx = fmaxf(mx, __shfl_xor_sync(0xffffffffu, mx, o));
    if ((t & 31) == 0) red[t >> 5] = mx;
    __syncthreads();
    if (t == 0) {
        float m = red[0];
#pragma unroll
        for (int i = 1; i < 8; i++) m = fmaxf(m, red[i]);
        bc = m;
    }
    __syncthreads();
    float M = bc, sum = 0.0f;
#pragma unroll
    for (int it = 0; it < 8; it++) {
        int g = t + it*256;
        if (g >= NG8) break;
        int l8 = g << 3;
        float e[8];
#pragma unroll
        for (int k = 0; k < 8; k++) { e[k] = fexp(sreg[it][k] - M); sum += e[k]; }
        *(float4*)(D + l8)     = make_float4(e[0],e[1],e[2],e[3]);
        *(float4*)(D + l8 + 4) = make_float4(e[4],e[5],e[6],e[7]);
    }
#pragma unroll
    for (int o = 16; o > 0; o >>= 1) sum += __shfl_xor_sync(0xffffffffu, sum, o);
    if ((t & 31) == 0) red[t >> 5] = sum;
    __syncthreads();
    if (t == 0) {
        float s = 0.0f;
#pragma unroll
        for (int i = 0; i < 8; i++) s += red[i];
        g_invs[b*NQ + q] = 1.0f / s;
    }
}

// ---------------- W V pass: W[q,l] = sum_dy H_P[q+dy*64, l+dy*st] ----------------
__global__ __launch_bounds__(256) void k_WV() {
    int q = blockIdx.x, b = blockIdx.y;
    const float* S = g_G + GUARD + (size_t)b*NQ*LPAD2;   // H_P
    float* D = g_H + GUARD + ((size_t)b*NQ + q)*LPAD2;   // W
    int y = q >> 6;
    const float* up = S + (size_t)(q-64)*LPAD2;
    const float* md = S + (size_t)q*LPAD2;
    const float* dn = S + (size_t)(q+64)*LPAD2;
    bool uok = y > 0, dok = y < 63;
    for (int g = threadIdx.x; g < NG8; g += 256) {
        int l8 = g << 3;
        int st = stride_of(l8);
        float acc[8], w[8];
        float4 m0 = *(const float4*)(md + l8), m1 = *(const float4*)(md + l8 + 4);
        acc[0]=m0.x; acc[1]=m0.y; acc[2]=m0.z; acc[3]=m0.w;
        acc[4]=m1.x; acc[5]=m1.y; acc[6]=m1.z; acc[7]=m1.w;
        if (uok) { ldwin8(up + l8 - st, w);
#pragma unroll
            for (int e = 0; e < 8; e++) acc[e] += w[e]; }
        if (dok) { ldwin8(dn + l8 + st, w);
#pragma unroll
            for (int e = 0; e < 8; e++) acc[e] += w[e]; }
        *(float4*)(D + l8)     = make_float4(acc[0],acc[1],acc[2],acc[3]);
        *(float4*)(D + l8 + 4) = make_float4(acc[4],acc[5],acc[6],acc[7]);
    }
}

// ---------------- out_part = W * base^T (split-K=8) ----------------
__global__ __launch_bounds__(256) void k_gemm_W() {
    const int split = blockIdx.x;
    const int bm = blockIdx.y << 7;
    const int b  = blockIdx.z;
    const float* W  = g_H + GUARD + (size_t)b*NQ*LPAD2;
    const float* Bb = g_base + (size_t)b*64*LPAD2;
    __shared__ float As[8][128];
    __shared__ float Bs[8][64];
    const int t = threadIdx.x;
    const int ty = t >> 4, tx = t & 15;
    float acc[8][4] = {};
    const int kbeg = split * (LPAD2/8);
    const int arow = t >> 1, akc = (t & 1) << 2;
    const float* Aptr = W + (size_t)(bm + arow)*LPAD2 + akc;
    const int brow = (t & 127) >> 1;
    const float* Bptr = Bb + (size_t)brow*LPAD2 + akc;
    for (int k0 = kbeg; k0 < kbeg + LPAD2/8; k0 += 8) {
        float4 a4 = *(const float4*)(Aptr + k0);
        As[akc+0][arow] = a4.x; As[akc+1][arow] = a4.y;
        As[akc+2][arow] = a4.z; As[akc+3][arow] = a4.w;
        if (t < 128) {
            float4 b4 = *(const float4*)(Bptr + k0);
            Bs[akc+0][brow] = b4.x; Bs[akc+1][brow] = b4.y;
            Bs[akc+2][brow] = b4.z; Bs[akc+3][brow] = b4.w;
        }
        __syncthreads();
#pragma unroll
        for (int kk = 0; kk < 8; kk++) {
            float4 a0 = *(const float4*)&As[kk][ty << 3];
            float4 a1 = *(const float4*)&As[kk][(ty << 3) + 4];
            float4 b0 = *(const float4*)&Bs[kk][tx << 2];
            float ra[8] = {a0.x,a0.y,a0.z,a0.w,a1.x,a1.y,a1.z,a1.w};
            float rb[4] = {b0.x,b0.y,b0.z,b0.w};
#pragma unroll
            for (int i = 0; i < 8; i++)
#pragma unroll
                for (int j = 0; j < 4; j++)
                    acc[i][j] = fmaf(ra[i], rb[j], acc[i][j]);
        }
        __syncthreads();
    }
    float* pb = g_part + (size_t)(split*2 + b)*64*NQ;
#pragma unroll
    for (int j = 0; j < 4; j++) {
        int c = (tx << 2) + j;
        *(float4*)(pb + (size_t)c*NQ + bm + (ty << 3))     = make_float4(acc[0][j],acc[1][j],acc[2][j],acc[3][j]);
        *(float4*)(pb + (size_t)c*NQ + bm + (ty << 3) + 4) = make_float4(acc[4][j],acc[5][j],acc[6][j],acc[7][j]);
    }
}

// ---------------- reduce + residual ----------------
__global__ void k_final(const float* __restrict__ inp, float* __restrict__ out) {
    int idx = blockIdx.x * blockDim.x + threadIdx.x;
    if (idx >= 2*64*4096) return;
    int q = idx & 4095, c = (idx >> 12) & 63, b = idx >> 18;
    float s = 0.0f;
#pragma unroll
    for (int sp = 0; sp < 8; sp++)
        s += g_part[(size_t)(sp*2 + b)*64*NQ + (size_t)c*NQ + q];
    out[idx] = inp[idx] + 0.25f * s;
}

extern "C" void kernel_launch(void* const* d_in, const int* in_sizes, int n_in,
                              void* d_out, int out_size) {
    const float* input     = (const float*)d_in[0];
    const float* input_ref = (const float*)d_in[1];
    const float* Wb  = (const float*)d_in[2];
    const float* bbv = (const float*)d_in[3];
    const float* Wm  = (const float*)d_in[4];
    const float* bmv = (const float*)d_in[5];
    const float* Wa  = (const float*)d_in[6];
    const float* bav = (const float*)d_in[7];
    const float* ap  = (const float*)d_in[8];
    float* out = (float*)d_out;

    k_zero       <<<1024, 256>>>();
    k_matchbase  <<<1024, 256>>>(input, Wb, bbv, ap);
    k_resize_conv<<<dim3(1666, 2), 128>>>(input_ref, Wm, bmv, Wa, bav, ap);
    k_prep       <<<dim3(113, 2), 128>>>();
    k_invb       <<<dim3(113, 2), 128>>>();
    k_gemm_G     <<<dim3(113, 32, 2), 256>>>();
    k_H<0>       <<<dim3(NQ, 2), 256>>>();   // H_G = x-shift of G
    k_scoreV     <<<dim3(NQ, 2), 256>>>();   // scores -> E + invs
    k_H<1>       <<<dim3(NQ, 2), 256>>>();   // H_P = x-shift of P (E*invs)
    k_WV         <<<dim3(NQ, 2), 256>>>();   // W = y-shift of H_P
    k_gemm_W     <<<dim3(8, 32, 2), 256>>>();
    k_final      <<<2048, 256>>>(input, out);
}